// round 12
// baseline (speedup 1.0000x reference)
#include <cuda_runtime.h>
#include <math.h>

// MultiHeadsAttModel: hyperbolic (Poincare-ball) multi-head attention.
// out = concat( out f32 [4,2000,32], att f32 [4,2000,5,5] )
// Launches:
//   0) init: zero per-agent coverage counters + phi-done counter
//   1) fused kernel, heterogeneous grid:
//        blocks [0,1000): phi role  -- per-node embedding phi(m)
//        blocks [1000,10766): scan role -- stream one-hot rows; the block that
//          COMPLETES an agent's 2500-uint4 range (per-agent atomic counter vs
//          analytic expected-toucher count) runs that agent's attention+layer2
//          inline, hidden under the HBM-bound stream.

#define BB   4
#define NN   2000
#define KK   5
#define DD   32
#define M1   160
#define MINN 1e-15f
#define MAXN 0.996f    // (1 - 4e-3)/sqrt(c), c = 1

#define SCAN_T   256
#define SCAN_B8  8
#define BLK4     (SCAN_T * SCAN_B8)          // 2048 uint4 per scan block
#define TOT4     ((BB * NN * KK * NN) / 4)   // 20,000,000 uint4
#define SCAN_BLOCKS ((TOT4 + BLK4 - 1) / BLK4)  // 9766
#define A4       ((KK * NN) / 4)             // 2500 uint4 per agent

#define NNODE (BB * NN)                       // 8000
#define WPB   8                               // warps per phi block
#define PHI_BLOCKS (NNODE / WPB)              // 1000
#define SKST 161                              // padded kv row stride

__device__ int   g_nei[NNODE * KK];           // 40000 neighbor indices
__device__ float g_phi[NNODE * M1];           // 8000 x 160 node embeddings
__device__ int   g_agent_cnt[NNODE];          // scan coverage counters
__device__ int   g_phi_done;                  // phi blocks completed

__device__ __forceinline__ float artanhf_(float x) {
    const float lim = 1.0f - 1e-7f;
    x = fminf(fmaxf(x, -lim), lim);
    return 0.5f * (log1pf(x) - log1pf(-x));
}

__device__ __forceinline__ float wsum(float x) {
    #pragma unroll
    for (int o = 16; o > 0; o >>= 1) x += __shfl_xor_sync(0xffffffffu, x, o);
    return x;
}

// ---------------- init: zero counters (runs each launch; replay-safe) ----------------
__global__ void init_kernel() {
    int i = blockIdx.x * blockDim.x + threadIdx.x;
    if (i < NNODE) g_agent_cnt[i] = 0;
    if (i == NNODE) g_phi_done = 0;
}

// ---------------- per-agent attention + layer 2 (one warp) ----------------
__device__ void do_att(int bn, int lane,
                       float (*skvw)[SKST], float* sattw,
                       const float* __restrict__ W2,
                       const float* __restrict__ b2,
                       float* __restrict__ out,
                       float* __restrict__ att_out) {
    // wait for all phi blocks (bids 0..999 dispatch before any scan block: no deadlock)
    if (lane == 0) {
        while (*(volatile int*)&g_phi_done < PHI_BLOCKS) __nanosleep(64);
    }
    __syncwarp();
    __threadfence();

    const int b = bn / NN;
    // gather q(phi[bn]) and kv(phi[neighbors])
    #pragma unroll
    for (int v = 0; v < 6; v++) {
        int row = (v == 0) ? bn : b * NN + g_nei[bn * KK + v - 1];
        #pragma unroll
        for (int j = 0; j < 5; j++)
            skvw[v][lane + 32 * j] = g_phi[row * M1 + lane + 32 * j];
    }
    __syncwarp();

    // logits: lane < 25 -> (hd = lane/5, k = lane%5)
    if (lane < 25) {
        int hd = lane / 5, k = lane - hd * 5;
        float l = 0.f;
        #pragma unroll 8
        for (int d = 0; d < DD; d++)
            l += skvw[0][d * 5 + hd] * skvw[k + 1][d * 5 + hd];
        sattw[lane] = l;
    }
    __syncwarp();
    if (lane < 5) {
        float m = -1e30f;
        #pragma unroll
        for (int k = 0; k < 5; k++) m = fmaxf(m, sattw[lane * 5 + k]);
        float e[5], s = 0.f;
        #pragma unroll
        for (int k = 0; k < 5; k++) { e[k] = expf(sattw[lane * 5 + k] - m); s += e[k]; }
        float inv = 1.f / s;
        #pragma unroll
        for (int k = 0; k < 5; k++) {
            float a = e[k] * inv;
            sattw[lane * 5 + k] = a;
            if (att_out) att_out[(size_t)bn * 25 + lane * 5 + k] = a;
        }
    }
    __syncwarp();

    // head-mean output (lane = output dim d)
    float o = 0.f;
    #pragma unroll
    for (int hd = 0; hd < 5; hd++) {
        float acc = 0.f;
        #pragma unroll
        for (int k = 0; k < 5; k++)
            acc += sattw[hd * 5 + k] * skvw[k + 1][lane * 5 + hd];
        o += acc;
    }
    o *= 0.2f;

    // hb2 = proj(expmap0(b2))
    float bt2 = b2[lane];
    float hbv, hbn22;
    {
        float n2b = wsum(bt2 * bt2);
        float bnn = fmaxf(sqrtf(n2b), MINN);
        float e  = tanhf(bnn) / bnn;
        float pn = e * bnn;
        float pj = (pn > MAXN) ? MAXN / pn : 1.f;
        float f  = e * pj;
        hbv = bt2 * f;
        hbn22 = f * f * n2b;
    }

    // W2 row for this lane (L1-hot, 4 KB total)
    float w2r[DD];
    {
        const float4* wv = (const float4*)(W2 + lane * DD);
        #pragma unroll
        for (int q = 0; q < 8; q++) {
            float4 v = wv[q];
            w2r[q * 4 + 0] = v.x; w2r[q * 4 + 1] = v.y;
            w2r[q * 4 + 2] = v.z; w2r[q * 4 + 3] = v.w;
        }
    }

    // layer 2
    float n2 = wsum(o * o);
    float xn = fmaxf(sqrtf(n2), MINN);
    float e  = tanhf(xn) / xn;
    float pn = e * xn;
    float pj = (pn > MAXN) ? MAXN / pn : 1.f;
    float p   = e * pj * o;                    // proj(expmap0(out32))
    float p2n = fmaxf(pj * pn, MINN);
    float m = 0.f;
    #pragma unroll
    for (int dd = 0; dd < DD; dd++) {
        float pd = __shfl_sync(0xffffffffu, p, dd);
        m += w2r[dd] * pd;                     // W2 @ p  (lane owns row `lane`)
    }
    float mxn2 = wsum(m * m);
    float mh   = wsum(m * hbv);
    float mxn  = fmaxf(sqrtf(mxn2), MINN);
    float rfac = (mxn2 == 0.f) ? 0.f : tanhf(mxn / p2n * artanhf_(p2n)) / mxn;
    float rn  = rfac * mxn;
    float pjr = (rn > MAXN) ? MAXN / fmaxf(rn, MINN) : 1.f;
    float g   = pjr * rfac;
    float x2  = g * g * mxn2;
    float xy  = g * mh;
    float y2  = hbn22;
    float A   = 1.f + 2.f * xy + y2;
    float Bc  = 1.f - x2;
    float den = fmaxf(1.f + 2.f * xy + x2 * y2, MINN);
    float c_  = (A * g * m + Bc * hbv) / den;
    float cn2 = wsum(c_ * c_);
    float cn  = fmaxf(sqrtf(cn2), MINN);
    float pj2 = (cn > MAXN) ? MAXN / cn : 1.f;
    float nnc = fmaxf(pj2 * cn, MINN);
    float u   = artanhf_(nnc) / nnc * pj2 * c_;
    float xtv = fmaxf(u, 0.f);
    float xn2 = wsum(xtv * xtv);
    float nx  = fmaxf(sqrtf(xn2), MINN);
    float ef  = tanhf(nx) / nx;
    float en  = ef * nx;
    float pj3 = (en > MAXN) ? MAXN / en : 1.f;
    out[(size_t)bn * DD + lane] = pj3 * ef * xtv;
}

// ---------------- fused kernel: phi role + scan(+inline att) role ----------------
__global__ void __launch_bounds__(SCAN_T)
fused_kernel(const uint4* __restrict__ nei,
             const float* __restrict__ in_feats,
             const float* __restrict__ W1,
             const float* __restrict__ b1,
             const float* __restrict__ W2,
             const float* __restrict__ b2,
             float* __restrict__ out,
             float* __restrict__ att_out) {
    // smem union: phi role uses W1s (32 x 161 = 5152 floats);
    // scan role uses skv (2 x 6 x 161 = 1932) + satt (64) within the same buffer.
    __shared__ __align__(16) float smem_f[DD * (M1 + 1)];

    const int tid  = threadIdx.x;
    const int lane = tid & 31;
    const int warp = tid >> 5;

    if (blockIdx.x >= PHI_BLOCKS) {
        // ================= scan role =================
        unsigned sb = blockIdx.x - PHI_BLOCKS;
        unsigned b0 = sb * BLK4 + tid;
        uint4 v[SCAN_B8];
        #pragma unroll
        for (int j = 0; j < SCAN_B8; j++) {
            unsigned i = b0 + j * SCAN_T;
            v[j] = (i < TOT4) ? __ldcs(nei + i) : make_uint4(0u, 0u, 0u, 0u);
        }
        #pragma unroll
        for (int j = 0; j < SCAN_B8; j++) {
            uint4 u = v[j];
            if ((u.x | u.y | u.z | u.w) != 0u) {
                unsigned i = b0 + j * SCAN_T;        // uint4 index; 2000 % 4 == 0
                unsigned r = i / 500u;               // flat row = bn*KK + k
                unsigned c4 = i * 4u - r * 2000u;
                unsigned c = c4 + (u.x ? 0u : (u.y ? 1u : (u.z ? 2u : 3u)));
                g_nei[r] = (int)c;
            }
        }
        __threadfence();

        // agent-completion accounting (each agent = 2500 uint4; block = 2048)
        __shared__ int comp_cnt;
        __shared__ int comp_agent[2];
        __syncthreads();
        if (tid == 0) {
            comp_cnt = 0;
            unsigned B0 = sb * BLK4;
            unsigned B1 = B0 + BLK4; if (B1 > TOT4) B1 = TOT4;
            unsigned a0 = B0 / A4, a1 = (B1 - 1) / A4;
            for (unsigned a = a0; a <= a1; a++) {
                unsigned expc = (A4 * a + A4 - 1) / BLK4 - (A4 * a) / BLK4 + 1u;
                int old = atomicAdd(&g_agent_cnt[a], 1);
                if (old + 1 == (int)expc) comp_agent[comp_cnt++] = (int)a;
            }
        }
        __syncthreads();
        int nc = comp_cnt;
        if (warp < nc) {
            float (*skvw)[SKST] = (float (*)[SKST])(smem_f + warp * 6 * SKST);
            float* sattw = smem_f + 2 * 6 * SKST + warp * 32;
            do_att(comp_agent[warp], lane, skvw, sattw, W2, b2, out, att_out);
        }
        return;
    }

    // ================= phi role: per-node embedding, warp-autonomous =================
    float (*W1s)[M1 + 1] = (float (*)[M1 + 1])smem_f;   // W1s[d][r] = W1[r][d]
    for (int i = tid; i < M1 * DD; i += 32 * WPB) W1s[i & 31][i >> 5] = W1[i];
    __syncthreads();

    const int node = blockIdx.x * WPB + warp;      // < 8000

    // hb1 = proj(expmap0(b1)); lane owns rows lane+32j
    float b1v[5];
    float bsq = 0.f;
    #pragma unroll
    for (int j = 0; j < 5; j++) { b1v[j] = b1[lane + 32 * j]; bsq += b1v[j] * b1v[j]; }
    float bn2 = wsum(bsq);
    float hbn2;
    {
        float bnn = fmaxf(sqrtf(bn2), MINN);
        float e  = tanhf(bnn) / bnn;
        float pn = e * bnn;
        float pj = (pn > MAXN) ? MAXN / pn : 1.f;
        float f  = e * pj;
        hbn2 = f * f * bn2;
        #pragma unroll
        for (int j = 0; j < 5; j++) b1v[j] *= f;
    }

    // p = proj(expmap0(logmap0(x)))
    float x  = in_feats[node * DD + lane];
    float n2 = wsum(x * x);
    float ps, xnc;
    {
        float xn = fmaxf(sqrtf(n2), MINN);
        float f1 = artanhf_(xn) / xn;            // logmap0
        float fn = fmaxf(f1 * xn, MINN);
        float e  = tanhf(fn) / fn;               // expmap0
        float pn = e * fn;
        float pj = (pn > MAXN) ? MAXN / pn : 1.f;
        ps  = f1 * e * pj;
        xnc = fmaxf(pj * pn, MINN);
    }
    float p = ps * x;

    // mx = W1 @ p : lane owns rows lane+32j
    float mx[5] = {0.f, 0.f, 0.f, 0.f, 0.f};
    #pragma unroll
    for (int d = 0; d < DD; d++) {
        float pd = __shfl_sync(0xffffffffu, p, d);
        #pragma unroll
        for (int j = 0; j < 5; j++) mx[j] += W1s[d][lane + 32 * j] * pd;
    }

    float s1 = 0.f, s2 = 0.f;
    #pragma unroll
    for (int j = 0; j < 5; j++) { s1 += mx[j] * mx[j]; s2 += mx[j] * b1v[j]; }
    float mxn2 = wsum(s1);
    float mh   = wsum(s2);

    float cA, cB;
    {
        float mxn  = fmaxf(sqrtf(mxn2), MINN);
        float rfac = (mxn2 == 0.f) ? 0.f
                   : tanhf(mxn / xnc * artanhf_(xnc)) / mxn;       // mobius_matvec
        float rn = rfac * mxn;
        float pj = (rn > MAXN) ? MAXN / fmaxf(rn, MINN) : 1.f;     // proj
        float g  = pj * rfac;
        float x2 = g * g * mxn2;
        float xy = g * mh;
        float y2 = hbn2;
        float A   = 1.f + 2.f * xy + y2;
        float Bc  = 1.f - x2;
        float den = fmaxf(1.f + 2.f * xy + x2 * y2, MINN);         // mobius_add
        cA = A * g / den;
        cB = Bc / den;
    }

    float cv[5];
    float c1 = 0.f, c2 = 0.f;
    #pragma unroll
    for (int j = 0; j < 5; j++) {
        cv[j] = cA * mx[j] + cB * b1v[j];
        float pp = fmaxf(cv[j], 0.f);
        c1 += cv[j] * cv[j];
        c2 += pp * pp;
    }
    float cn2  = wsum(c1);
    float pos2 = wsum(c2);
    float ql;
    {
        float cn = fmaxf(sqrtf(cn2), MINN);
        float pj = (cn > MAXN) ? MAXN / cn : 1.f;
        float nn = fmaxf(pj * cn, MINN);
        float l  = pj * artanhf_(nn) / nn;         // logmap0(proj(res)); l >= 0
        float nx = fmaxf(l * sqrtf(pos2), MINN);   // ||relu(l*cv)||
        float ef = tanhf(nx) / nx;
        float en = ef * nx;
        float pj2 = (en > MAXN) ? MAXN / en : 1.f;
        float fn = fmaxf(pj2 * en, MINN);
        ql = artanhf_(fn) / fn * pj2 * ef * l;
    }
    #pragma unroll
    for (int j = 0; j < 5; j++)
        g_phi[node * M1 + lane + 32 * j] = ql * fmaxf(cv[j], 0.f);

    // publish phi completion
    __threadfence();
    __syncthreads();
    if (tid == 0) atomicAdd(&g_phi_done, 1);
}

extern "C" void kernel_launch(void* const* d_in, const int* in_sizes, int n_in,
                              void* d_out, int out_size) {
    const float* in_feats = (const float*)d_in[0];
    const float* in_nei   = (const float*)d_in[1];
    const float* W1       = (const float*)d_in[2];
    const float* b1       = (const float*)d_in[3];
    const float* W2       = (const float*)d_in[4];
    const float* b2       = (const float*)d_in[5];
    float* out = (float*)d_out;
    const int out_elems = BB * NN * DD;                 // 256000
    const int att_elems = BB * NN * 25;                 // 200000
    float* att = (out_size >= out_elems + att_elems) ? out + out_elems : nullptr;

    init_kernel<<<(NNODE + 256) / 256, 256>>>();
    fused_kernel<<<PHI_BLOCKS + SCAN_BLOCKS, SCAN_T>>>(
        (const uint4*)in_nei, in_feats, W1, b1, W2, b2, out, att);
}